// round 13
// baseline (speedup 1.0000x reference)
#include <cuda_runtime.h>
#include <cuda_bf16.h>
#include <cstdint>

#define BB 16
#define LL 2048
#define DDIM 64
#define MT 64           // q rows per CTA
#define NTILE 64        // k cols per tile
#define NTILES 32
#define NTHREADS 128    // 2x2 warps, each 32 rows x 32 cols
#define LOG2E 1.4426950408889634f

#define K_F4 524288
#define V_F4 524288

#define TILE_BYTES 16384u     // [mat:2][n:64][128B]
#define SM_SCR (3 * 16384)    // 128-float row-sum scratch
#define SMEM_BYTES (3 * 16384 + 512)

__device__ __nv_bfloat16 g_k_hi[BB * LL * DDIM];
__device__ __nv_bfloat16 g_k_lo[BB * LL * DDIM];

// ---------------- PTX helpers (generic-target safe) ----------------
__device__ __forceinline__ void cp16(uint32_t dst, const void* src) {
    asm volatile("cp.async.cg.shared.global [%0], [%1], 16;\n" :: "r"(dst), "l"(src));
}
__device__ __forceinline__ void cp_commit() {
    asm volatile("cp.async.commit_group;\n");
}
template <int N>
__device__ __forceinline__ void cp_wait() {
    asm volatile("cp.async.wait_group %0;\n" :: "n"(N));
}
__device__ __forceinline__ float ex2(float x) {
    float r;
    asm("ex2.approx.f32 %0, %1;" : "=f"(r) : "f"(x));
    return r;
}

#define LDSM4(r0, r1, r2, r3, addr)                                        \
    asm volatile("ldmatrix.sync.aligned.m8n8.x4.shared.b16 {%0,%1,%2,%3}, [%4];" \
                 : "=r"(r0), "=r"(r1), "=r"(r2), "=r"(r3) : "r"(addr))

#define MMA_BF16(c, a, b0, b1)                                             \
    asm volatile("mma.sync.aligned.m16n8k16.row.col.f32.bf16.bf16.f32 "    \
                 "{%0,%1,%2,%3}, {%4,%5,%6,%7}, {%8,%9}, {%0,%1,%2,%3};"   \
                 : "+f"((c)[0]), "+f"((c)[1]), "+f"((c)[2]), "+f"((c)[3])  \
                 : "r"((a)[0]), "r"((a)[1]), "r"((a)[2]), "r"((a)[3]),     \
                   "r"(b0), "r"(b1))

__device__ __forceinline__ uint32_t pack2(float a, float b) {
    __nv_bfloat162 t = __floats2bfloat162_rn(a, b);
    return *reinterpret_cast<uint32_t*>(&t);
}
__device__ __forceinline__ uint32_t pack_hi(float2 f) {
    return pack2(f.x, f.y);
}
__device__ __forceinline__ uint32_t pack_lo(float2 f) {
    float hx = __bfloat162float(__float2bfloat16_rn(f.x));
    float hy = __bfloat162float(__float2bfloat16_rn(f.y));
    return pack2(f.x - hx, f.y - hy);
}

// ------- prep: k -> bf16 hi/lo scratch; v -> out (fused) -------
__global__ void __launch_bounds__(256)
prep_kernel(const float4* __restrict__ k4, const float4* __restrict__ v4,
            float4* __restrict__ outv4) {
    int idx = blockIdx.x * 256 + threadIdx.x;
    if (idx < K_F4) {
        float4 f = k4[idx];
        float hx = __bfloat162float(__float2bfloat16_rn(f.x));
        float hy = __bfloat162float(__float2bfloat16_rn(f.y));
        float hz = __bfloat162float(__float2bfloat16_rn(f.z));
        float hw = __bfloat162float(__float2bfloat16_rn(f.w));
        uint2 hi, lo;
        hi.x = pack2(f.x, f.y);            hi.y = pack2(f.z, f.w);
        lo.x = pack2(f.x - hx, f.y - hy);  lo.y = pack2(f.z - hz, f.w - hw);
        reinterpret_cast<uint2*>(g_k_hi)[idx] = hi;
        reinterpret_cast<uint2*>(g_k_lo)[idx] = lo;
    } else {
        int j = idx - K_F4;
        outv4[j] = v4[j];
    }
}

// ------- k tile loader: 1024 cp16 by 128 threads -------
__device__ __forceinline__ void load_k_tile(uint32_t sb, int b, int tile,
                                            int buf, int tid) {
    const size_t base = ((size_t)b * LL + (size_t)tile * NTILE) * DDIM;
    #pragma unroll
    for (int rep = 0; rep < 8; rep++) {
        int cidx = tid + rep * NTHREADS;   // 0..1023
        int m = cidx >> 9;                 // 0=hi, 1=lo
        int rem = cidx & 511;
        int n = rem >> 3, ch = rem & 7;
        const __nv_bfloat16* src =
            (m ? g_k_lo : g_k_hi) + base + (size_t)n * DDIM + ch * 8;
        uint32_t dst = sb + (uint32_t)buf * TILE_BYTES + (uint32_t)m * 8192u
                     + (uint32_t)n * 128u + (uint32_t)((ch ^ (n & 7)) << 4);
        cp16(dst, src);
    }
}

struct Frag { uint32_t ahi[2][4][4]; uint32_t alo[2][4][4]; };

// ------- core: 32 rows x 32 cols per warp, 96 MMAs -------
__device__ __forceinline__ void compute_tile(
    float C[2][4][4], uint32_t tb, const Frag& fr,
    int rr, int cs, int nb, int wc)
{
    #pragma unroll
    for (int mb = 0; mb < 2; mb++)
        #pragma unroll
        for (int i = 0; i < 4; i++)
            C[mb][i][0] = C[mb][i][1] = C[mb][i][2] = C[mb][i][3] = 0.f;

    uint32_t rowoffs[2];
    #pragma unroll
    for (int j = 0; j < 2; j++)
        rowoffs[j] = (uint32_t)(wc * 32 + j * 16 + nb) * 128u;

    #pragma unroll
    for (int ks = 0; ks < 4; ks++) {
        const uint32_t choff = (uint32_t)((((ks << 1) | cs) ^ rr) << 4);
        uint32_t f0[2], f1[2], f2[2], f3[2];

        // hi B frags: feed ahi & alo for both m-blocks -> 16 MMAs
        #pragma unroll
        for (int j = 0; j < 2; j++)
            LDSM4(f0[j], f1[j], f2[j], f3[j], tb + rowoffs[j] + choff);
        #pragma unroll
        for (int j = 0; j < 2; j++) MMA_BF16(C[0][2*j],   fr.ahi[0][ks], f0[j], f1[j]);
        #pragma unroll
        for (int j = 0; j < 2; j++) MMA_BF16(C[0][2*j+1], fr.ahi[0][ks], f2[j], f3[j]);
        #pragma unroll
        for (int j = 0; j < 2; j++) MMA_BF16(C[1][2*j],   fr.ahi[1][ks], f0[j], f1[j]);
        #pragma unroll
        for (int j = 0; j < 2; j++) MMA_BF16(C[1][2*j+1], fr.ahi[1][ks], f2[j], f3[j]);
        #pragma unroll
        for (int j = 0; j < 2; j++) MMA_BF16(C[0][2*j],   fr.alo[0][ks], f0[j], f1[j]);
        #pragma unroll
        for (int j = 0; j < 2; j++) MMA_BF16(C[0][2*j+1], fr.alo[0][ks], f2[j], f3[j]);
        #pragma unroll
        for (int j = 0; j < 2; j++) MMA_BF16(C[1][2*j],   fr.alo[1][ks], f0[j], f1[j]);
        #pragma unroll
        for (int j = 0; j < 2; j++) MMA_BF16(C[1][2*j+1], fr.alo[1][ks], f2[j], f3[j]);

        // lo B frags: feed ahi for both m-blocks -> 8 MMAs
        #pragma unroll
        for (int j = 0; j < 2; j++)
            LDSM4(f0[j], f1[j], f2[j], f3[j], tb + 8192u + rowoffs[j] + choff);
        #pragma unroll
        for (int j = 0; j < 2; j++) MMA_BF16(C[0][2*j],   fr.ahi[0][ks], f0[j], f1[j]);
        #pragma unroll
        for (int j = 0; j < 2; j++) MMA_BF16(C[0][2*j+1], fr.ahi[0][ks], f2[j], f3[j]);
        #pragma unroll
        for (int j = 0; j < 2; j++) MMA_BF16(C[1][2*j],   fr.ahi[1][ks], f0[j], f1[j]);
        #pragma unroll
        for (int j = 0; j < 2; j++) MMA_BF16(C[1][2*j+1], fr.ahi[1][ks], f2[j], f3[j]);
    }
}

// ---------------- attention kernel ----------------
__global__ void __launch_bounds__(NTHREADS, 3)
attn_mma_kernel(const float* __restrict__ q, float* __restrict__ out_attn) {
    extern __shared__ char smem[];
    const uint32_t sb = (uint32_t)__cvta_generic_to_shared(smem);
    float* scr = reinterpret_cast<float*>(smem + SM_SCR);   // [2][64]
    const int tid = threadIdx.x;
    const int w = tid >> 5;
    const int l = tid & 31;
    const int wr = w & 1;        // row group (32 rows)
    const int wc = w >> 1;       // col group (32 cols)
    const int b = blockIdx.y;
    const int qt = blockIdx.x;

    // prologue: tiles 0,1 in flight
    load_k_tile(sb, b, 0, 0, tid);
    cp_commit();
    load_k_tile(sb, b, 1, 1, tid);
    cp_commit();

    // A fragments: rows 32*wr .. +31 (two m16 blocks)
    Frag fr;
    #pragma unroll
    for (int mb = 0; mb < 2; mb++) {
        const float* q0 = q + ((size_t)b * LL + (size_t)qt * MT
                               + wr * 32 + mb * 16 + (l >> 2)) * DDIM;
        #pragma unroll
        for (int ks = 0; ks < 4; ks++) {
            const int c0 = ks * 16 + (l & 3) * 2;
            float2 p00 = *(const float2*)(q0 + c0);
            float2 p10 = *(const float2*)(q0 + 8 * DDIM + c0);
            float2 p01 = *(const float2*)(q0 + c0 + 8);
            float2 p11 = *(const float2*)(q0 + 8 * DDIM + c0 + 8);
            p00.x *= LOG2E; p00.y *= LOG2E;
            p10.x *= LOG2E; p10.y *= LOG2E;
            p01.x *= LOG2E; p01.y *= LOG2E;
            p11.x *= LOG2E; p11.y *= LOG2E;
            fr.ahi[mb][ks][0] = pack_hi(p00);  fr.alo[mb][ks][0] = pack_lo(p00);
            fr.ahi[mb][ks][1] = pack_hi(p10);  fr.alo[mb][ks][1] = pack_lo(p10);
            fr.ahi[mb][ks][2] = pack_hi(p01);  fr.alo[mb][ks][2] = pack_lo(p01);
            fr.ahi[mb][ks][3] = pack_hi(p11);  fr.alo[mb][ks][3] = pack_lo(p11);
        }
    }

    const int rr = l & 7;
    const int mi = l >> 3;
    const int cs = mi & 1;
    const int nb = ((mi >> 1) << 3) + rr;

    const int r0i = 32 * wr + (l >> 2);   // CTA-local row of C[0][.][0,1]

    float s0 = 0.f, s1 = 0.f, s2 = 0.f, s3 = 0.f;

    float* orow0 = out_attn + ((size_t)b * LL + (size_t)qt * MT + r0i) * (size_t)LL;
    float* orow1 = orow0 + (size_t)8 * LL;
    float* orow2 = orow0 + (size_t)16 * LL;
    float* orow3 = orow0 + (size_t)24 * LL;

    // =================== pass A: row sums of exp2 ===================
    for (int it = 0; it < NTILES; it++) {
        const int buf = it % 3;
        cp_wait<1>();
        __syncthreads();

        load_k_tile(sb, b, (it + 2) & 31, (it + 2) % 3, tid);
        cp_commit();

        float C[2][4][4];
        compute_tile(C, sb + (uint32_t)buf * TILE_BYTES, fr, rr, cs, nb, wc);

        #pragma unroll
        for (int nf = 0; nf < 4; nf++) {
            s0 += ex2(C[0][nf][0]) + ex2(C[0][nf][1]);
            s1 += ex2(C[0][nf][2]) + ex2(C[0][nf][3]);
            s2 += ex2(C[1][nf][0]) + ex2(C[1][nf][1]);
            s3 += ex2(C[1][nf][2]) + ex2(C[1][nf][3]);
        }
    }

    // combine col-lane partials, publish per-col-half sums, combine halves
    {
        s0 += __shfl_xor_sync(0xFFFFFFFFu, s0, 1);
        s0 += __shfl_xor_sync(0xFFFFFFFFu, s0, 2);
        s1 += __shfl_xor_sync(0xFFFFFFFFu, s1, 1);
        s1 += __shfl_xor_sync(0xFFFFFFFFu, s1, 2);
        s2 += __shfl_xor_sync(0xFFFFFFFFu, s2, 1);
        s2 += __shfl_xor_sync(0xFFFFFFFFu, s2, 2);
        s3 += __shfl_xor_sync(0xFFFFFFFFu, s3, 1);
        s3 += __shfl_xor_sync(0xFFFFFFFFu, s3, 2);
        if ((l & 3) == 0) {
            scr[wc * 64 + r0i]      = s0;
            scr[wc * 64 + r0i + 8]  = s1;
            scr[wc * 64 + r0i + 16] = s2;
            scr[wc * 64 + r0i + 24] = s3;
        }
    }
    __syncthreads();
    const float inv0 = 1.0f / (scr[r0i]      + scr[64 + r0i]);
    const float inv1 = 1.0f / (scr[r0i + 8]  + scr[64 + r0i + 8]);
    const float inv2 = 1.0f / (scr[r0i + 16] + scr[64 + r0i + 16]);
    const float inv3 = 1.0f / (scr[r0i + 24] + scr[64 + r0i + 24]);

    // =================== pass B: recompute, normalize, store ===================
    for (int g = NTILES; g < 2 * NTILES; g++) {
        const int buf = g % 3;
        const int tile = g & 31;
        cp_wait<1>();
        __syncthreads();

        if (g + 2 < 2 * NTILES) {
            load_k_tile(sb, b, (g + 2) & 31, (g + 2) % 3, tid);
            cp_commit();
        } else {
            cp_commit();
        }

        float C[2][4][4];
        compute_tile(C, sb + (uint32_t)buf * TILE_BYTES, fr, rr, cs, nb, wc);

        const int colb = tile * NTILE + 32 * wc + ((l & 3) << 1);
        #pragma unroll
        for (int nf = 0; nf < 4; nf++) {
            const int co = colb + nf * 8;
            float2 v;
            v.x = ex2(C[0][nf][0]) * inv0;
            v.y = ex2(C[0][nf][1]) * inv0;
            *(float2*)(orow0 + co) = v;
            v.x = ex2(C[0][nf][2]) * inv1;
            v.y = ex2(C[0][nf][3]) * inv1;
            *(float2*)(orow1 + co) = v;
            v.x = ex2(C[1][nf][0]) * inv2;
            v.y = ex2(C[1][nf][1]) * inv2;
            *(float2*)(orow2 + co) = v;
            v.x = ex2(C[1][nf][2]) * inv3;
            v.y = ex2(C[1][nf][3]) * inv3;
            *(float2*)(orow3 + co) = v;
        }
    }
}

extern "C" void kernel_launch(void* const* d_in, const int* in_sizes, int n_in,
                              void* d_out, int out_size) {
    const float* q = (const float*)d_in[0];
    const float* k = (const float*)d_in[1];
    const float* v = (const float*)d_in[2];
    float* out = (float*)d_out;

    const size_t v_elems = (size_t)BB * LL * DDIM;

    prep_kernel<<<(K_F4 + V_F4) / 256, 256>>>((const float4*)k,
                                              (const float4*)v,
                                              (float4*)out);

    cudaFuncSetAttribute(attn_mma_kernel,
                         cudaFuncAttributeMaxDynamicSharedMemorySize, SMEM_BYTES);
    dim3 grid(LL / MT, BB);   // (32, 16) = 512 CTAs
    attn_mma_kernel<<<grid, NTHREADS, SMEM_BYTES>>>(q, out + v_elems);
}

// round 14
// speedup vs baseline: 1.0041x; 1.0041x over previous
#include <cuda_runtime.h>
#include <cuda_bf16.h>
#include <cstdint>

#define BB 16
#define LL 2048
#define DDIM 64
#define MT 64           // q rows per CTA
#define NTILE 64        // k cols per tile
#define NTILES 32
#define NTHREADS 128    // 2x2 warps, each 32 rows x 32 cols
#define LOG2E 1.4426950408889634f

#define K_F4 524288
#define V_F4 524288

#define TILE_BYTES 16384u     // [mat:2][n:64][128B]
#define SM_SCR (3 * 16384)
#define SMEM_BYTES (3 * 16384 + 512)

__device__ __nv_bfloat16 g_k_hi[BB * LL * DDIM];
__device__ __nv_bfloat16 g_k_lo[BB * LL * DDIM];

// ---------------- PTX helpers (generic-target safe) ----------------
__device__ __forceinline__ void cp16(uint32_t dst, const void* src) {
    asm volatile("cp.async.cg.shared.global [%0], [%1], 16;\n" :: "r"(dst), "l"(src));
}
__device__ __forceinline__ void cp_commit() {
    asm volatile("cp.async.commit_group;\n");
}
template <int N>
__device__ __forceinline__ void cp_wait() {
    asm volatile("cp.async.wait_group %0;\n" :: "n"(N));
}
__device__ __forceinline__ float ex2(float x) {
    float r;
    asm("ex2.approx.f32 %0, %1;" : "=f"(r) : "f"(x));
    return r;
}

#define LDSM4(r0, r1, r2, r3, addr)                                        \
    asm volatile("ldmatrix.sync.aligned.m8n8.x4.shared.b16 {%0,%1,%2,%3}, [%4];" \
                 : "=r"(r0), "=r"(r1), "=r"(r2), "=r"(r3) : "r"(addr))

#define MMA_BF16(c, a, b0, b1)                                             \
    asm volatile("mma.sync.aligned.m16n8k16.row.col.f32.bf16.bf16.f32 "    \
                 "{%0,%1,%2,%3}, {%4,%5,%6,%7}, {%8,%9}, {%0,%1,%2,%3};"   \
                 : "+f"((c)[0]), "+f"((c)[1]), "+f"((c)[2]), "+f"((c)[3])  \
                 : "r"((a)[0]), "r"((a)[1]), "r"((a)[2]), "r"((a)[3]),     \
                   "r"(b0), "r"(b1))

__device__ __forceinline__ uint32_t pack2(float a, float b) {
    __nv_bfloat162 t = __floats2bfloat162_rn(a, b);
    return *reinterpret_cast<uint32_t*>(&t);
}
__device__ __forceinline__ uint32_t pack_hi(float2 f) {
    return pack2(f.x, f.y);
}
__device__ __forceinline__ uint32_t pack_lo(float2 f) {
    float hx = __bfloat162float(__float2bfloat16_rn(f.x));
    float hy = __bfloat162float(__float2bfloat16_rn(f.y));
    return pack2(f.x - hx, f.y - hy);
}

// ------- prep: k -> bf16 hi/lo scratch; v -> out (fused) -------
__global__ void __launch_bounds__(256)
prep_kernel(const float4* __restrict__ k4, const float4* __restrict__ v4,
            float4* __restrict__ outv4) {
    int idx = blockIdx.x * 256 + threadIdx.x;
    if (idx < K_F4) {
        float4 f = k4[idx];
        float hx = __bfloat162float(__float2bfloat16_rn(f.x));
        float hy = __bfloat162float(__float2bfloat16_rn(f.y));
        float hz = __bfloat162float(__float2bfloat16_rn(f.z));
        float hw = __bfloat162float(__float2bfloat16_rn(f.w));
        uint2 hi, lo;
        hi.x = pack2(f.x, f.y);            hi.y = pack2(f.z, f.w);
        lo.x = pack2(f.x - hx, f.y - hy);  lo.y = pack2(f.z - hz, f.w - hw);
        reinterpret_cast<uint2*>(g_k_hi)[idx] = hi;
        reinterpret_cast<uint2*>(g_k_lo)[idx] = lo;
    } else {
        int j = idx - K_F4;
        outv4[j] = v4[j];
    }
}

// ------- k tile loader: 1024 cp16 by 128 threads -------
__device__ __forceinline__ void load_k_tile(uint32_t sb, int b, int tile,
                                            int buf, int tid) {
    const size_t base = ((size_t)b * LL + (size_t)tile * NTILE) * DDIM;
    #pragma unroll
    for (int rep = 0; rep < 8; rep++) {
        int cidx = tid + rep * NTHREADS;
        int m = cidx >> 9;
        int rem = cidx & 511;
        int n = rem >> 3, ch = rem & 7;
        const __nv_bfloat16* src =
            (m ? g_k_lo : g_k_hi) + base + (size_t)n * DDIM + ch * 8;
        uint32_t dst = sb + (uint32_t)buf * TILE_BYTES + (uint32_t)m * 8192u
                     + (uint32_t)n * 128u + (uint32_t)((ch ^ (n & 7)) << 4);
        cp16(dst, src);
    }
}

struct Frag { uint32_t ahi[2][4][4]; uint32_t alo[2][4][4]; };

// ------- core: 32 rows x 32 cols per warp, 96 MMAs -------
__device__ __forceinline__ void compute_tile(
    float C[2][4][4], uint32_t tb, const Frag& fr,
    int rr, int cs, int nb, int wc)
{
    #pragma unroll
    for (int mb = 0; mb < 2; mb++)
        #pragma unroll
        for (int i = 0; i < 4; i++)
            C[mb][i][0] = C[mb][i][1] = C[mb][i][2] = C[mb][i][3] = 0.f;

    uint32_t rowoffs[2];
    #pragma unroll
    for (int j = 0; j < 2; j++)
        rowoffs[j] = (uint32_t)(wc * 32 + j * 16 + nb) * 128u;

    #pragma unroll
    for (int ks = 0; ks < 4; ks++) {
        const uint32_t choff = (uint32_t)((((ks << 1) | cs) ^ rr) << 4);
        uint32_t f0[2], f1[2], f2[2], f3[2];

        #pragma unroll
        for (int j = 0; j < 2; j++)
            LDSM4(f0[j], f1[j], f2[j], f3[j], tb + rowoffs[j] + choff);
        #pragma unroll
        for (int j = 0; j < 2; j++) MMA_BF16(C[0][2*j],   fr.ahi[0][ks], f0[j], f1[j]);
        #pragma unroll
        for (int j = 0; j < 2; j++) MMA_BF16(C[0][2*j+1], fr.ahi[0][ks], f2[j], f3[j]);
        #pragma unroll
        for (int j = 0; j < 2; j++) MMA_BF16(C[1][2*j],   fr.ahi[1][ks], f0[j], f1[j]);
        #pragma unroll
        for (int j = 0; j < 2; j++) MMA_BF16(C[1][2*j+1], fr.ahi[1][ks], f2[j], f3[j]);
        #pragma unroll
        for (int j = 0; j < 2; j++) MMA_BF16(C[0][2*j],   fr.alo[0][ks], f0[j], f1[j]);
        #pragma unroll
        for (int j = 0; j < 2; j++) MMA_BF16(C[0][2*j+1], fr.alo[0][ks], f2[j], f3[j]);
        #pragma unroll
        for (int j = 0; j < 2; j++) MMA_BF16(C[1][2*j],   fr.alo[1][ks], f0[j], f1[j]);
        #pragma unroll
        for (int j = 0; j < 2; j++) MMA_BF16(C[1][2*j+1], fr.alo[1][ks], f2[j], f3[j]);

        #pragma unroll
        for (int j = 0; j < 2; j++)
            LDSM4(f0[j], f1[j], f2[j], f3[j], tb + 8192u + rowoffs[j] + choff);
        #pragma unroll
        for (int j = 0; j < 2; j++) MMA_BF16(C[0][2*j],   fr.ahi[0][ks], f0[j], f1[j]);
        #pragma unroll
        for (int j = 0; j < 2; j++) MMA_BF16(C[0][2*j+1], fr.ahi[0][ks], f2[j], f3[j]);
        #pragma unroll
        for (int j = 0; j < 2; j++) MMA_BF16(C[1][2*j],   fr.ahi[1][ks], f0[j], f1[j]);
        #pragma unroll
        for (int j = 0; j < 2; j++) MMA_BF16(C[1][2*j+1], fr.ahi[1][ks], f2[j], f3[j]);
    }
}

// deferred epilogues
#define EPI_A(C)                                                      \
    do {                                                              \
        _Pragma("unroll")                                             \
        for (int nf = 0; nf < 4; nf++) {                              \
            s0 += ex2(C[0][nf][0]) + ex2(C[0][nf][1]);                \
            s1 += ex2(C[0][nf][2]) + ex2(C[0][nf][3]);                \
            s2 += ex2(C[1][nf][0]) + ex2(C[1][nf][1]);                \
            s3 += ex2(C[1][nf][2]) + ex2(C[1][nf][3]);                \
        }                                                             \
    } while (0)

#define EPI_B(C, tile)                                                \
    do {                                                              \
        const int colb = (tile) * NTILE + 32 * wc + ((l & 3) << 1);   \
        _Pragma("unroll")                                             \
        for (int nf = 0; nf < 4; nf++) {                              \
            const int co = colb + nf * 8;                             \
            float2 v;                                                 \
            v.x = ex2(C[0][nf][0]) * inv0;                            \
            v.y = ex2(C[0][nf][1]) * inv0;                            \
            *(float2*)(orow0 + co) = v;                               \
            v.x = ex2(C[0][nf][2]) * inv1;                            \
            v.y = ex2(C[0][nf][3]) * inv1;                            \
            *(float2*)(orow1 + co) = v;                               \
            v.x = ex2(C[1][nf][0]) * inv2;                            \
            v.y = ex2(C[1][nf][1]) * inv2;                            \
            *(float2*)(orow2 + co) = v;                               \
            v.x = ex2(C[1][nf][2]) * inv3;                            \
            v.y = ex2(C[1][nf][3]) * inv3;                            \
            *(float2*)(orow3 + co) = v;                               \
        }                                                             \
    } while (0)

// advance pipeline half-step: wait tile seq, sync, prefetch seq+2
#define PIPE_STEP(seq)                                                \
    do {                                                              \
        cp_wait<1>();                                                 \
        __syncthreads();                                              \
        if ((seq) + 2 < 64) {                                         \
            load_k_tile(sb, b, ((seq) + 2) & 31, ((seq) + 2) % 3, tid); \
        }                                                             \
        cp_commit();                                                  \
    } while (0)

// ---------------- attention kernel ----------------
__global__ void __launch_bounds__(NTHREADS, 2)
attn_mma_kernel(const float* __restrict__ q, float* __restrict__ out_attn) {
    extern __shared__ char smem[];
    const uint32_t sb = (uint32_t)__cvta_generic_to_shared(smem);
    float* scr = reinterpret_cast<float*>(smem + SM_SCR);
    const int tid = threadIdx.x;
    const int w = tid >> 5;
    const int l = tid & 31;
    const int wr = w & 1;
    const int wc = w >> 1;
    const int b = blockIdx.y;
    const int qt = blockIdx.x;

    load_k_tile(sb, b, 0, 0, tid);
    cp_commit();
    load_k_tile(sb, b, 1, 1, tid);
    cp_commit();

    Frag fr;
    #pragma unroll
    for (int mb = 0; mb < 2; mb++) {
        const float* q0 = q + ((size_t)b * LL + (size_t)qt * MT
                               + wr * 32 + mb * 16 + (l >> 2)) * DDIM;
        #pragma unroll
        for (int ks = 0; ks < 4; ks++) {
            const int c0 = ks * 16 + (l & 3) * 2;
            float2 p00 = *(const float2*)(q0 + c0);
            float2 p10 = *(const float2*)(q0 + 8 * DDIM + c0);
            float2 p01 = *(const float2*)(q0 + c0 + 8);
            float2 p11 = *(const float2*)(q0 + 8 * DDIM + c0 + 8);
            p00.x *= LOG2E; p00.y *= LOG2E;
            p10.x *= LOG2E; p10.y *= LOG2E;
            p01.x *= LOG2E; p01.y *= LOG2E;
            p11.x *= LOG2E; p11.y *= LOG2E;
            fr.ahi[mb][ks][0] = pack_hi(p00);  fr.alo[mb][ks][0] = pack_lo(p00);
            fr.ahi[mb][ks][1] = pack_hi(p10);  fr.alo[mb][ks][1] = pack_lo(p10);
            fr.ahi[mb][ks][2] = pack_hi(p01);  fr.alo[mb][ks][2] = pack_lo(p01);
            fr.ahi[mb][ks][3] = pack_hi(p11);  fr.alo[mb][ks][3] = pack_lo(p11);
        }
    }

    const int rr = l & 7;
    const int mi = l >> 3;
    const int cs = mi & 1;
    const int nb = ((mi >> 1) << 3) + rr;
    const int r0i = 32 * wr + (l >> 2);

    float s0 = 0.f, s1 = 0.f, s2 = 0.f, s3 = 0.f;

    float* orow0 = out_attn + ((size_t)b * LL + (size_t)qt * MT + r0i) * (size_t)LL;
    float* orow1 = orow0 + (size_t)8 * LL;
    float* orow2 = orow0 + (size_t)16 * LL;
    float* orow3 = orow0 + (size_t)24 * LL;

    float CA[2][4][4], CB[2][4][4];
    // CB initialized so its premature pass-A epilogue contributes exactly 0
    #pragma unroll
    for (int mb = 0; mb < 2; mb++)
        #pragma unroll
        for (int i = 0; i < 4; i++)
            CB[mb][i][0] = CB[mb][i][1] = CB[mb][i][2] = CB[mb][i][3] = -1e30f;

    // ============ pass A: row sums of exp2 (epilogue deferred 1 tile) ============
    for (int p = 0; p < 16; p++) {
        const int sA = 2 * p;       // seq of CA tile
        const int sB = 2 * p + 1;   // seq of CB tile

        PIPE_STEP(sA);
        compute_tile(CA, sb + (uint32_t)(sA % 3) * TILE_BYTES, fr, rr, cs, nb, wc);
        EPI_A(CB);                  // tile sB-2 (or zeros at p=0)

        PIPE_STEP(sB);
        compute_tile(CB, sb + (uint32_t)(sB % 3) * TILE_BYTES, fr, rr, cs, nb, wc);
        EPI_A(CA);                  // tile sA
    }
    EPI_A(CB);                      // tile 31

    // combine col-lane partials; publish per-col-half; combine halves
    {
        s0 += __shfl_xor_sync(0xFFFFFFFFu, s0, 1);
        s0 += __shfl_xor_sync(0xFFFFFFFFu, s0, 2);
        s1 += __shfl_xor_sync(0xFFFFFFFFu, s1, 1);
        s1 += __shfl_xor_sync(0xFFFFFFFFu, s1, 2);
        s2 += __shfl_xor_sync(0xFFFFFFFFu, s2, 1);
        s2 += __shfl_xor_sync(0xFFFFFFFFu, s2, 2);
        s3 += __shfl_xor_sync(0xFFFFFFFFu, s3, 1);
        s3 += __shfl_xor_sync(0xFFFFFFFFu, s3, 2);
        if ((l & 3) == 0) {
            scr[wc * 64 + r0i]      = s0;
            scr[wc * 64 + r0i + 8]  = s1;
            scr[wc * 64 + r0i + 16] = s2;
            scr[wc * 64 + r0i + 24] = s3;
        }
    }
    __syncthreads();
    const float inv0 = 1.0f / (scr[r0i]      + scr[64 + r0i]);
    const float inv1 = 1.0f / (scr[r0i + 8]  + scr[64 + r0i + 8]);
    const float inv2 = 1.0f / (scr[r0i + 16] + scr[64 + r0i + 16]);
    const float inv3 = 1.0f / (scr[r0i + 24] + scr[64 + r0i + 24]);

    // ============ pass B: recompute, normalize, store (deferred 1 tile) ============
    for (int p = 0; p < 16; p++) {
        const int sA = 32 + 2 * p;
        const int sB = 33 + 2 * p;

        PIPE_STEP(sA);
        compute_tile(CA, sb + (uint32_t)(sA % 3) * TILE_BYTES, fr, rr, cs, nb, wc);
        if (p != 0) EPI_B(CB, (sB - 2) & 31);

        PIPE_STEP(sB);
        compute_tile(CB, sb + (uint32_t)(sB % 3) * TILE_BYTES, fr, rr, cs, nb, wc);
        EPI_B(CA, sA & 31);
    }
    EPI_B(CB, 31);
}

extern "C" void kernel_launch(void* const* d_in, const int* in_sizes, int n_in,
                              void* d_out, int out_size) {
    const float* q = (const float*)d_in[0];
    const float* k = (const float*)d_in[1];
    const float* v = (const float*)d_in[2];
    float* out = (float*)d_out;

    const size_t v_elems = (size_t)BB * LL * DDIM;

    prep_kernel<<<(K_F4 + V_F4) / 256, 256>>>((const float4*)k,
                                              (const float4*)v,
                                              (float4*)out);

    cudaFuncSetAttribute(attn_mma_kernel,
                         cudaFuncAttributeMaxDynamicSharedMemorySize, SMEM_BYTES);
    dim3 grid(LL / MT, BB);   // (32, 16) = 512 CTAs
    attn_mma_kernel<<<grid, NTHREADS, SMEM_BYTES>>>(q, out + v_elems);
}